// round 1
// baseline (speedup 1.0000x reference)
#include <cuda_runtime.h>

#define N_POS   1024
#define BDIM    256
#define SPLIT   8
#define MAX_BLK 1024
#define KTOP    10

// Scratch (allocation-free, graph-replay safe: every slot rewritten each launch)
__device__ float g_partial[MAX_BLK];
__device__ int   g_count[MAX_BLK];

__global__ __launch_bounds__(BDIM) void lambdarank_pairs(
    const float* __restrict__ scores, const int* __restrict__ rels, int N)
{
    __shared__ float  s_score[N_POS];
    __shared__ int    s_rel[N_POS];
    __shared__ float2 relSD[N_POS];   // compacted (score, disc) for relevant items
    __shared__ float2 nonSD[N_POS];   // compacted (score, disc) for non-relevant items
    __shared__ int    sh_cnt[2];
    __shared__ float  red[BDIM];

    const int b    = blockIdx.x / SPLIT;
    const int s    = blockIdx.x % SPLIT;
    const int t    = threadIdx.x;
    const int lane = t & 31;
    const int wid  = t >> 5;

    // Stage this batch's row in shared memory (coalesced)
    for (int p = t; p < N; p += BDIM) {
        s_score[p] = scores[b * N + p];
        s_rel[p]   = rels[b * N + p];
    }
    __syncthreads();

    // Deterministic stable compaction: warp 0 -> rel list, warp 1 -> nonrel list
    if (wid < 2) {
        const bool want_rel = (wid == 0);
        int base = 0;
        for (int it = 0; it < N; it += 32) {
            int p = it + lane;
            bool hit = ((s_rel[p] != 0) == want_rel);
            unsigned m = __ballot_sync(0xffffffffu, hit);
            int pre = __popc(m & ((1u << lane) - 1u));
            if (hit) {
                float d = 1.0f / log2f((float)p + 2.0f);   // DCG discount at position p
                float2 v = make_float2(s_score[p], d);
                if (want_rel) relSD[base + pre] = v;
                else          nonSD[base + pre] = v;
            }
            base += __popc(m);
        }
        if (lane == 0) sh_cnt[wid] = base;
    }
    __syncthreads();

    const int nrel = sh_cnt[0];
    const int nnon = sh_cnt[1];

    float thread_sum = 0.0f;
    int   blk_count  = 0;

    if (nrel > 0 && nnon > 0) {
        // Ideal DCG@10 (binary gains: top-min(nrel,10) positions)
        float idcg = 0.0f;
        const int kk = (nrel < KTOP) ? nrel : KTOP;
        #pragma unroll
        for (int k = 0; k < KTOP; k++)
            if (k < kk) idcg += 1.0f / log2f((float)k + 2.0f);
        const float inv_idcg = 1.0f / (idcg + 1e-8f);

        // exact #pairs handled by this block (j strided by SPLIT starting at s)
        const int cntj = (nnon > s) ? ((nnon - 1 - s) / SPLIT + 1) : 0;
        blk_count = nrel * cntj;

        for (int i0 = 0; i0 < nrel; i0 += BDIM) {
            // skip warps with no valid i (tail handling)
            if (i0 + (wid << 5) >= nrel) continue;
            const int  i = i0 + t;
            const bool v = (i < nrel);
            const float2 rd = v ? relSD[i] : make_float2(0.0f, 0.0f);
            const float si = rd.x, di = rd.y;

            float acc = 0.0f;
            #pragma unroll 4
            for (int j = s; j < nnon; j += SPLIT) {
                float2 nd = nonSD[j];                 // one LDS.64 broadcast per warp
                float z  = nd.x - si;                 // sj - si  (= -SIGMA * s_diff)
                float e  = __expf(-fabsf(z));
                float l2 = __log2f(1.0f + e);
                float sp = fmaf(l2, 0.69314718055994531f, fmaxf(z, 0.0f)); // softplus(z)
                float w  = fabsf(di - nd.y);          // |disc_i - disc_j|
                acc = fmaf(w, sp, acc);
            }
            if (v) thread_sum += acc;
        }
        thread_sum *= inv_idcg;
    }

    // Deterministic block reduction
    red[t] = thread_sum;
    __syncthreads();
    for (int off = BDIM >> 1; off > 0; off >>= 1) {
        if (t < off) red[t] += red[t + off];
        __syncthreads();
    }
    if (t == 0) {
        g_partial[blockIdx.x] = red[0];
        g_count[blockIdx.x]   = blk_count;
    }
}

__global__ void lambdarank_finalize(float* __restrict__ out, int nblocks)
{
    __shared__ float     ssum[512];
    __shared__ long long scnt[512];
    const int t = threadIdx.x;
    float s = 0.0f;
    long long c = 0;
    for (int i = t; i < nblocks; i += 512) {
        s += g_partial[i];
        c += (long long)g_count[i];
    }
    ssum[t] = s; scnt[t] = c;
    __syncthreads();
    for (int off = 256; off > 0; off >>= 1) {
        if (t < off) { ssum[t] += ssum[t + off]; scnt[t] += scnt[t + off]; }
        __syncthreads();
    }
    if (t == 0)
        out[0] = (scnt[0] > 0) ? (ssum[0] / (float)scnt[0]) : 0.0f;
}

extern "C" void kernel_launch(void* const* d_in, const int* in_sizes, int n_in,
                              void* d_out, int out_size)
{
    const float* scores = (const float*)d_in[0];
    const int*   rels   = (const int*)d_in[1];

    const int N = N_POS;                 // fixed problem shape [B, 1024]
    const int B = in_sizes[0] / N;       // 64
    const int nblocks = B * SPLIT;       // 512

    lambdarank_pairs<<<nblocks, BDIM>>>(scores, rels, N);
    lambdarank_finalize<<<1, 512>>>((float*)d_out, nblocks);
}

// round 2
// speedup vs baseline: 1.4095x; 1.4095x over previous
#include <cuda_runtime.h>

#define N_POS   1024
#define BDIM    256
#define SPLIT   8
#define MAX_BLK 1024
#define KTOP    10

// Scratch (allocation-free; every slot used is rewritten each launch)
__device__ float    g_partial[MAX_BLK];
__device__ int      g_count[MAX_BLK];
__device__ unsigned g_ticket;   // zero-init; reset to 0 by the last block each launch

// idcg prefix table: idcg(kk) = sum_{k=0}^{kk-1} 1/log2(k+2), kk = min(nrel, 10)
__constant__ float c_idcg[11] = {
    0.0f,
    1.0f,
    1.6309297535714574f,
    2.1309297535714574f,
    2.5616063116448505f,
    2.9484591188793920f,
    3.3046663059874144f,
    3.6379996393207477f,
    3.9534645161064764f,
    4.2544945117704580f,
    4.5435593380883460f
};

__global__ __launch_bounds__(BDIM) void lambdarank_fused(
    const float* __restrict__ scores, const int* __restrict__ rels,
    const int N, const int nblocks, float* __restrict__ out)
{
    __shared__ float  s_score[N_POS];
    __shared__ int    s_rel[N_POS];
    __shared__ float2 relSD[N_POS];   // (e^{-si}, disc_i) for relevant items
    __shared__ float2 nonSD[N_POS];   // (e^{+sj}, disc_j) for non-relevant items
    __shared__ int    sh_cnt[2];
    __shared__ float  red_f[BDIM / 32];
    __shared__ int    red_i[BDIM / 32];
    __shared__ bool   s_last;

    const int b    = blockIdx.x / SPLIT;
    const int s    = blockIdx.x % SPLIT;
    const int t    = threadIdx.x;
    const int lane = t & 31;
    const int wid  = t >> 5;

    // Stage this batch's row (vectorized, coalesced)
    {
        const float4* sc4 = (const float4*)(scores + (size_t)b * N);
        const int4*   rl4 = (const int4*)(rels   + (size_t)b * N);
        for (int p = t; p < N / 4; p += BDIM) {
            ((float4*)s_score)[p] = sc4[p];
            ((int4*)s_rel)[p]     = rl4[p];
        }
    }
    __syncthreads();

    // Deterministic stable compaction (warp 0 -> rel, warp 1 -> nonrel),
    // storing precomputed exponentials so the pair loop needs only 1 MUFU/pair.
    if (wid < 2) {
        const bool want_rel = (wid == 0);
        int base = 0;
        for (int it = 0; it < N; it += 32) {
            int p = it + lane;
            bool hit = ((s_rel[p] != 0) == want_rel);
            unsigned m = __ballot_sync(0xffffffffu, hit);
            if (hit) {
                int pre = __popc(m & ((1u << lane) - 1u));
                float sc = s_score[p];
                float E  = __expf(want_rel ? -sc : sc);
                float d  = 1.0f / __log2f((float)p + 2.0f);  // DCG discount at position p
                float2 v = make_float2(E, d);
                if (want_rel) relSD[base + pre] = v;
                else          nonSD[base + pre] = v;
            }
            base += __popc(m);
        }
        if (lane == 0) sh_cnt[wid] = base;
    }
    __syncthreads();

    const int nrel = sh_cnt[0];
    const int nnon = sh_cnt[1];

    float thread_sum = 0.0f;
    int   blk_count  = 0;

    if (nrel > 0 && nnon > 0) {
        const float idcg = c_idcg[(nrel < KTOP) ? nrel : KTOP];
        // softplus = ln2 * log2(1 + e^z); fold ln2 and 1/(idcg+eps) into one factor
        const float norm = 0.69314718055994531f / (idcg + 1e-8f);

        const int cntj = (nnon > s) ? ((nnon - 1 - s) / SPLIT + 1) : 0;
        blk_count = nrel * cntj;

        for (int i0 = 0; i0 < nrel; i0 += BDIM) {
            if (i0 + (wid << 5) >= nrel) continue;   // whole-warp tail skip
            const int  i = i0 + t;
            const bool v = (i < nrel);
            const float2 rd = v ? relSD[i] : make_float2(0.0f, 0.0f);
            const float Ei = rd.x, di = rd.y;        // Ei=0 => contributions are exactly 0

            float acc0 = 0.0f, acc1 = 0.0f;
            int j = s;
            #pragma unroll 4
            for (; j + SPLIT < nnon; j += 2 * SPLIT) {
                float2 a = nonSD[j];
                float2 c = nonSD[j + SPLIT];
                // log2(1 + Ej*Ei) : 1 FFMA + 1 MUFU.LG2 per pair
                acc0 = fmaf(fabsf(di - a.y), __log2f(fmaf(a.x, Ei, 1.0f)), acc0);
                acc1 = fmaf(fabsf(di - c.y), __log2f(fmaf(c.x, Ei, 1.0f)), acc1);
            }
            if (j < nnon) {
                float2 a = nonSD[j];
                acc0 = fmaf(fabsf(di - a.y), __log2f(fmaf(a.x, Ei, 1.0f)), acc0);
            }
            if (v) thread_sum += acc0 + acc1;
        }
        thread_sum *= norm;
    }

    // Deterministic block reduction (warp shuffles, fixed order)
    {
        float ws = thread_sum;
        #pragma unroll
        for (int o = 16; o > 0; o >>= 1) ws += __shfl_down_sync(0xffffffffu, ws, o);
        if (lane == 0) red_f[wid] = ws;
        __syncthreads();
        if (wid == 0) {
            float v2 = (lane < BDIM / 32) ? red_f[lane] : 0.0f;
            #pragma unroll
            for (int o = 4; o > 0; o >>= 1) v2 += __shfl_down_sync(0xffffffffu, v2, o);
            if (lane == 0) {
                g_partial[blockIdx.x] = v2;
                g_count[blockIdx.x]   = blk_count;
            }
        }
    }

    // Fused finalize: last block to arrive reduces all partials (fixed order).
    __threadfence();
    if (t == 0)
        s_last = (atomicAdd(&g_ticket, 1u) == (unsigned)(nblocks - 1));
    __syncthreads();

    if (s_last) {
        float fs = 0.0f;
        int   cs = 0;
        for (int idx = t; idx < nblocks; idx += BDIM) {
            fs += g_partial[idx];
            cs += g_count[idx];
        }
        #pragma unroll
        for (int o = 16; o > 0; o >>= 1) {
            fs += __shfl_down_sync(0xffffffffu, fs, o);
            cs += __shfl_down_sync(0xffffffffu, cs, o);
        }
        if (lane == 0) { red_f[wid] = fs; red_i[wid] = cs; }
        __syncthreads();
        if (t == 0) {
            float st = 0.0f; int ct = 0;
            #pragma unroll
            for (int w = 0; w < BDIM / 32; w++) { st += red_f[w]; ct += red_i[w]; }
            out[0] = (ct > 0) ? (st / (float)ct) : 0.0f;
            g_ticket = 0;   // reset for next graph replay
        }
    }
}

extern "C" void kernel_launch(void* const* d_in, const int* in_sizes, int n_in,
                              void* d_out, int out_size)
{
    const float* scores = (const float*)d_in[0];
    const int*   rels   = (const int*)d_in[1];

    const int N = N_POS;                 // fixed problem shape [B, 1024]
    const int B = in_sizes[0] / N;       // 64
    const int nblocks = B * SPLIT;       // 512

    lambdarank_fused<<<nblocks, BDIM>>>(scores, rels, N, nblocks, (float*)d_out);
}

// round 3
// speedup vs baseline: 1.7686x; 1.2548x over previous
#include <cuda_runtime.h>

#define N_POS   1024
#define BDIM    256
#define SPLIT   16
#define MAX_BLK 1024
#define KTOP    10
#define NWARP   (BDIM / 32)

// Scratch (allocation-free; every slot used is rewritten each launch)
__device__ float    g_partial[MAX_BLK];
__device__ int      g_count[MAX_BLK];
__device__ unsigned g_ticket;   // zero-init; reset to 0 by the last block each launch

// idcg prefix table: idcg(kk) = sum_{k=0}^{kk-1} 1/log2(k+2), kk = min(nrel, 10)
__constant__ float c_idcg[11] = {
    0.0f, 1.0f, 1.6309297535714574f, 2.1309297535714574f,
    2.5616063116448505f, 2.9484591188793920f, 3.3046663059874144f,
    3.6379996393207477f, 3.9534645161064764f, 4.2544945117704580f,
    4.5435593380883460f
};

__global__ __launch_bounds__(BDIM) void lambdarank_fused(
    const float* __restrict__ scores, const int* __restrict__ rels,
    const int nblocks, float* __restrict__ out)
{
    __shared__ float  s_score[N_POS];
    __shared__ int    s_rel[N_POS];
    __shared__ float2 relSD[N_POS];          // (e^{-si}, disc_i) for relevant items
    __shared__ float2 nonSD[N_POS + 64];     // (e^{+sj}, disc_j) + zero padding
    __shared__ int    sh_cntR[NWARP], sh_baseR[NWARP], sh_baseN[NWARP];
    __shared__ int    sh_tot[2];
    __shared__ float  red_f[NWARP];
    __shared__ int    red_i[NWARP];
    __shared__ bool   s_last;

    const int b    = blockIdx.x / SPLIT;
    const int s    = blockIdx.x % SPLIT;
    const int t    = threadIdx.x;
    const int lane = t & 31;
    const int wid  = t >> 5;
    const unsigned lt_mask = (1u << lane) - 1u;

    // ---- Stage this batch's row (vectorized, coalesced) ----
    {
        const float4* sc4 = (const float4*)(scores + (size_t)b * N_POS);
        const int4*   rl4 = (const int4*)(rels   + (size_t)b * N_POS);
        for (int p = t; p < N_POS / 4; p += BDIM) {
            ((float4*)s_score)[p] = sc4[p];
            ((int4*)s_rel)[p]     = rl4[p];
        }
    }
    __syncthreads();

    // ---- Parallel deterministic stable compaction (all 8 warps) ----
    // Each warp owns a 128-position chunk (4 ballot iterations).
    unsigned masks[4];
    {
        int cr = 0;
        #pragma unroll
        for (int it = 0; it < 4; it++) {
            int p = (wid << 7) + (it << 5) + lane;
            unsigned m = __ballot_sync(0xffffffffu, s_rel[p] != 0);
            masks[it] = m;
            cr += __popc(m);
        }
        if (lane == 0) sh_cntR[wid] = cr;
    }
    __syncthreads();
    if (t == 0) {
        int aR = 0, aN = 0;
        #pragma unroll
        for (int w = 0; w < NWARP; w++) {
            sh_baseR[w] = aR; sh_baseN[w] = aN;
            aR += sh_cntR[w]; aN += 128 - sh_cntR[w];
        }
        sh_tot[0] = aR; sh_tot[1] = aN;
    }
    __syncthreads();
    {
        int rb = sh_baseR[wid], nb = sh_baseN[wid];
        #pragma unroll
        for (int it = 0; it < 4; it++) {
            int p = (wid << 7) + (it << 5) + lane;
            unsigned m = masks[it];
            bool hit = (m >> lane) & 1u;
            float sc = s_score[p];
            float E  = __expf(hit ? -sc : sc);
            float d  = 1.0f / __log2f((float)p + 2.0f);   // DCG discount @ position p
            float2 v = make_float2(E, d);
            int preR = __popc(m & lt_mask);
            if (hit) relSD[rb + preR]              = v;
            else     nonSD[nb + (lane - preR)]     = v;
            rb += __popc(m);
            nb += 32 - __popc(m);
        }
    }
    __syncthreads();

    const int nrel = sh_tot[0];
    const int nnon = sh_tot[1];

    // Zero-pad nonSD: E=0 entries contribute exactly 0 (log2(1+0)=0)
    if (t < 64) nonSD[nnon + t] = make_float2(0.0f, 0.0f);
    __syncthreads();

    float thread_sum = 0.0f;
    int   blk_count  = 0;

    if (nrel > 0 && nnon > 0) {
        const float idcg = c_idcg[(nrel < KTOP) ? nrel : KTOP];
        const float norm = 0.69314718055994531f / (idcg + 1e-8f);  // ln2 / (idcg+eps)

        // exact #pairs for this block (strided j slice), rounded trip count
        const int cntj  = (nnon > s) ? ((nnon - 1 - s) / SPLIT + 1) : 0;
        const int trips = (cntj + 3) & ~3;         // multiple of 4; padding absorbs extras
        blk_count = nrel * cntj;

        // i-register blocking: each thread owns i = ibase + 2t, ibase + 2t + 1
        for (int ibase = 0; ibase < nrel; ibase += 2 * BDIM) {
            if (ibase + (wid << 6) >= nrel) continue;   // whole-warp tail skip
            const int ia = ibase + 2 * t;
            const bool v0 = (ia     < nrel);
            const bool v1 = (ia + 1 < nrel);
            float4 rv = *(const float4*)&relSD[ia];      // in-bounds: ia+1 < N_POS
            const float Ei0 = v0 ? rv.x : 0.0f;
            const float di0 = v0 ? rv.y : 0.0f;
            const float Ei1 = v1 ? rv.z : 0.0f;
            const float di1 = v1 ? rv.w : 0.0f;

            float a0 = 0.0f, a1 = 0.0f;
            int j = s;
            #pragma unroll 4
            for (int k = 0; k < trips; k++, j += SPLIT) {
                float2 nd = nonSD[j];                    // LDS.64 broadcast
                float u0 = fmaf(nd.x, Ei0, 1.0f);
                float u1 = fmaf(nd.x, Ei1, 1.0f);
                a0 = fmaf(fabsf(di0 - nd.y), __log2f(u0), a0);
                a1 = fmaf(fabsf(di1 - nd.y), __log2f(u1), a1);
            }
            thread_sum += a0 + a1;
        }
        thread_sum *= norm;
    }

    // ---- Deterministic block reduction (warp shuffles, fixed order) ----
    {
        float ws = thread_sum;
        #pragma unroll
        for (int o = 16; o > 0; o >>= 1) ws += __shfl_down_sync(0xffffffffu, ws, o);
        if (lane == 0) red_f[wid] = ws;
        __syncthreads();
        if (wid == 0) {
            float v2 = (lane < NWARP) ? red_f[lane] : 0.0f;
            #pragma unroll
            for (int o = 4; o > 0; o >>= 1) v2 += __shfl_down_sync(0xffffffffu, v2, o);
            if (lane == 0) {
                g_partial[blockIdx.x] = v2;
                g_count[blockIdx.x]   = blk_count;
            }
        }
    }

    // ---- Fused finalize: last block reduces all partials (fixed order) ----
    __threadfence();
    if (t == 0)
        s_last = (atomicAdd(&g_ticket, 1u) == (unsigned)(nblocks - 1));
    __syncthreads();

    if (s_last) {
        float fs = 0.0f;
        int   cs = 0;
        for (int idx = t; idx < nblocks; idx += BDIM) {
            fs += g_partial[idx];
            cs += g_count[idx];
        }
        #pragma unroll
        for (int o = 16; o > 0; o >>= 1) {
            fs += __shfl_down_sync(0xffffffffu, fs, o);
            cs += __shfl_down_sync(0xffffffffu, cs, o);
        }
        if (lane == 0) { red_f[wid] = fs; red_i[wid] = cs; }
        __syncthreads();
        if (t == 0) {
            float st = 0.0f; int ct = 0;
            #pragma unroll
            for (int w = 0; w < NWARP; w++) { st += red_f[w]; ct += red_i[w]; }
            out[0] = (ct > 0) ? (st / (float)ct) : 0.0f;
            g_ticket = 0;   // reset for next graph replay
        }
    }
}

extern "C" void kernel_launch(void* const* d_in, const int* in_sizes, int n_in,
                              void* d_out, int out_size)
{
    const float* scores = (const float*)d_in[0];
    const int*   rels   = (const int*)d_in[1];

    const int B = in_sizes[0] / N_POS;   // 64
    const int nblocks = B * SPLIT;       // 1024

    lambdarank_fused<<<nblocks, BDIM>>>(scores, rels, nblocks, (float*)d_out);
}